// round 15
// baseline (speedup 1.0000x reference)
#include <cuda_runtime.h>
#include <cuda_fp16.h>
#include <cstdint>
#include <math.h>

#define BB 4
#define SS 2048
#define DD 1024

#define LDBY 144                    // smem row stride bytes (128B data + 16B pad)
#define TILE_BY (128 * LDBY)        // 18432 B : 128x64 fp16 tile
#define NSTAGE 3
#define STAGE_B (2 * TILE_BY)       // A, B per stage = 36864
#define SMEM_BYTES (NSTAGE * STAGE_B)   // 110592 per CTA; 2 CTAs/SM = 221184

// ---------------------------------------------------------------------------
// Scratch (__device__ globals; allocation-free rule)
// ---------------------------------------------------------------------------
__device__ __align__(16) __half g_x[BB*SS*DD];
__device__ __align__(16) __half g_w[3][DD*DD];
__device__ __align__(16) __half g_q[BB*SS*DD];
__device__ __align__(16) __half g_k[BB*SS*DD];
__device__ __align__(16) __half g_vT[BB*DD*SS];     // V^T [b][d][s]
__device__ __align__(16) __half g_ph[BB*SS*SS];     // p~ = exp(s/32), causal-masked
__device__ __align__(16) float  g_sum[BB*SS];       // row sums (atomic-accumulated)

// ---------------------------------------------------------------------------
// PTX primitives
// ---------------------------------------------------------------------------
__device__ __forceinline__ void mma_f16(float* d, const uint32_t* a, const uint32_t* b) {
    asm volatile(
        "mma.sync.aligned.m16n8k16.row.col.f32.f16.f16.f32 "
        "{%0,%1,%2,%3}, {%4,%5,%6,%7}, {%8,%9}, {%0,%1,%2,%3};"
        : "+f"(d[0]), "+f"(d[1]), "+f"(d[2]), "+f"(d[3])
        : "r"(a[0]), "r"(a[1]), "r"(a[2]), "r"(a[3]), "r"(b[0]), "r"(b[1]));
}
#define LDSM4(r0, r1, r2, r3, addr) \
    asm volatile("ldmatrix.sync.aligned.m8n8.x4.shared.b16 {%0,%1,%2,%3}, [%4];" \
                 : "=r"(r0), "=r"(r1), "=r"(r2), "=r"(r3) : "r"(addr))
#define CP_ASYNC16(dst, src) \
    asm volatile("cp.async.cg.shared.global [%0], [%1], 16;" :: "r"(dst), "l"(src))
#define CP_COMMIT() asm volatile("cp.async.commit_group;" ::: "memory")
#define CP_WAIT1()  asm volatile("cp.async.wait_group 1;" ::: "memory")

// ---------------------------------------------------------------------------
// cp.async: one 128x64 fp16 tile (K-major, row stride ld elems). 128 threads.
// ---------------------------------------------------------------------------
__device__ __forceinline__ void g2s_tile(uint32_t dst, const __half* __restrict__ g,
                                         size_t ld, int k0, int tid) {
#pragma unroll
    for (int i = 0; i < 8; i++) {
        int slot = tid + (i << 7);      // 0..1023
        int row = slot >> 3;            // 0..127
        int c = slot & 7;               // 16B chunk
        CP_ASYNC16(dst + row * LDBY + c * 16, g + (size_t)row * ld + k0 + c * 8);
    }
}

// ---------------------------------------------------------------------------
// Mainloop: acc[4][8][4] += A[128,K] . B[128,K]^T  (fp16, K-chunk 64)
// 128 threads, 4 warps 2x2, warp tile 64x64, 3-stage cp.async pipeline,
// ONE __syncthreads per chunk (compute-then-prefetch ordering).
// ---------------------------------------------------------------------------
__device__ __forceinline__ void mma_mainloop(
    const __half* __restrict__ A, const __half* __restrict__ B,
    size_t lda, size_t ldb, int nch, uint32_t smem, float acc[4][8][4]) {

    const int tid = threadIdx.x;
    const int lane = tid & 31, wid = tid >> 5;
    const int wm = wid >> 1, wn = wid & 1;

    const uint32_t a_off = (uint32_t)(wm * 64 + (lane & 15)) * LDBY + ((lane & 16) ? 16u : 0u);
    const uint32_t b_off = (uint32_t)(wn * 64 + (lane & 7) + ((lane & 16) ? 8 : 0)) * LDBY
                         + ((lane & 8) ? 16u : 0u);

    // prologue: chunks 0, 1
#pragma unroll
    for (int s = 0; s < 2; s++) {
        if (s < nch) {
            uint32_t st = smem + s * STAGE_B;
            g2s_tile(st,           A, lda, s * 64, tid);
            g2s_tile(st + TILE_BY, B, ldb, s * 64, tid);
        }
        CP_COMMIT();
    }

    int sidx = 0;
    for (int c = 0; c < nch; c++) {
        CP_WAIT1();
        __syncthreads();

        const uint32_t st = smem + sidx * STAGE_B;
#pragma unroll
        for (int ks = 0; ks < 4; ks++) {
            const uint32_t ka = st + a_off + ks * 32;
            const uint32_t kb = st + TILE_BY + b_off + ks * 32;
            uint32_t ah[4][4], bb[8][2];
#pragma unroll
            for (int fm = 0; fm < 4; fm++)
                LDSM4(ah[fm][0], ah[fm][1], ah[fm][2], ah[fm][3], ka + fm * 16 * LDBY);
#pragma unroll
            for (int p = 0; p < 4; p++)
                LDSM4(bb[2*p][0], bb[2*p][1], bb[2*p+1][0], bb[2*p+1][1], kb + p * 16 * LDBY);
#pragma unroll
            for (int fm = 0; fm < 4; fm++)
#pragma unroll
                for (int fn = 0; fn < 8; fn++) mma_f16(acc[fm][fn], ah[fm], bb[fn]);
        }

        // prefetch chunk c+2 into stage (sidx+2)%3
        if (c + 2 < nch) {
            int s2 = sidx + 2; if (s2 >= NSTAGE) s2 -= NSTAGE;
            uint32_t stw = smem + s2 * STAGE_B;
            const int k0 = (c + 2) * 64;
            g2s_tile(stw,           A, lda, k0, tid);
            g2s_tile(stw + TILE_BY, B, ldb, k0, tid);
        }
        CP_COMMIT();
        if (++sidx == NSTAGE) sidx = 0;
    }
}

#define ZERO_ACC(acc) \
    do { _Pragma("unroll") for (int i = 0; i < 4; i++) \
         _Pragma("unroll") for (int j = 0; j < 8; j++) \
         _Pragma("unroll") for (int r = 0; r < 4; r++) (acc)[i][j][r] = 0.0f; } while (0)

// ---------------------------------------------------------------------------
// Kernel 0: convert x, Wq, Wk, Wv to fp16 (float4 loads); zero g_sum
// ---------------------------------------------------------------------------
__global__ __launch_bounds__(256) void convert_all(
    const float* __restrict__ x, const float* __restrict__ wq,
    const float* __restrict__ wk, const float* __restrict__ wv) {
    const int which = blockIdx.y;
    const float* src = (which == 0) ? x : (which == 1) ? wq : (which == 2) ? wk : wv;
    __half* dst = (which == 0) ? g_x : g_w[which - 1];
    const int n4 = ((which == 0) ? BB * SS * DD : DD * DD) >> 2;
    for (int i = blockIdx.x * 256 + threadIdx.x; i < n4; i += gridDim.x * 256) {
        float4 f = *(const float4*)(src + i * 4);
        __half2 h0, h1;
        h0.x = __float2half(f.x); h0.y = __float2half(f.y);
        h1.x = __float2half(f.z); h1.y = __float2half(f.w);
        uint2 v; v.x = *(uint32_t*)&h0; v.y = *(uint32_t*)&h1;
        *(uint2*)(dst + i * 4) = v;
    }
    if (which == 0) {
        for (int i = blockIdx.x * 256 + threadIdx.x; i < BB * SS; i += gridDim.x * 256)
            g_sum[i] = 0.0f;
    }
}

// ---------------------------------------------------------------------------
// Kernel 1: Q, K projections only.  z=0 -> Q, z=1 -> K
// ---------------------------------------------------------------------------
__global__ __launch_bounds__(128, 2) void qkv_mma() {
    extern __shared__ char smraw[];
    const uint32_t smem = (uint32_t)__cvta_generic_to_shared(smraw);
    const int z = blockIdx.z;
    const int m0 = blockIdx.y * 128;
    const int n0 = blockIdx.x * 128;

    float acc[4][8][4];
    ZERO_ACC(acc);

    mma_mainloop(g_x + (size_t)m0 * DD, g_w[z] + (size_t)n0 * DD,
                 DD, DD, DD / 64, smem, acc);

    const int lane = threadIdx.x & 31, wid = threadIdx.x >> 5;
    const int wm = wid >> 1, wn = wid & 1;
    const int g = lane >> 2, tg = lane & 3;

    __half* D = z ? g_k : g_q;
#pragma unroll
    for (int fm = 0; fm < 4; fm++)
#pragma unroll
        for (int fn = 0; fn < 8; fn++) {
            const int n = n0 + wn * 64 + fn * 8 + tg * 2;
#pragma unroll
            for (int half = 0; half < 2; half++) {
                const int m = m0 + wm * 64 + fm * 16 + g + half * 8;
                __half2 h2;
                h2.x = __float2half(acc[fm][fn][half * 2]);
                h2.y = __float2half(acc[fm][fn][half * 2 + 1]);
                *(__half2*)(D + (size_t)m * DD + n) = h2;
            }
        }
}

// ---------------------------------------------------------------------------
// Kernel 2 (fused): t < 136  -> causal scores tile (p~ + row sums)
//                   t >= 136 -> V^T projection tile (smem-staged transpose)
// grid = (136 + 128, BB)
// ---------------------------------------------------------------------------
__global__ __launch_bounds__(128, 2) void scores_v_mma() {
    extern __shared__ char smraw[];
    const uint32_t smem = (uint32_t)__cvta_generic_to_shared(smraw);
    const int t = blockIdx.x;
    const int lane = threadIdx.x & 31, wid = threadIdx.x >> 5;
    const int wm = wid >> 1, wn = wid & 1;
    const int g = lane >> 2, tg = lane & 3;

    if (t >= 136) {
        // ---- V^T projection: u in 0..511 -> (m0 block, n0 block) ----
        const int u = (t - 136) + blockIdx.y * 128;
        const int n0 = (u & 7) * 128;
        const int m0 = (u >> 3) * 128;

        float acc[4][8][4];
        ZERO_ACC(acc);
        mma_mainloop(g_x + (size_t)m0 * DD, g_w[2] + (size_t)n0 * DD,
                     DD, DD, DD / 64, smem, acc);

        // transpose 128x128 tile through smem, then coalesced store to V^T
        __syncthreads();                      // mainloop smem reads done
        __half* smt = (__half*)smraw;         // [n_local][m_local], stride 136
#pragma unroll
        for (int fm = 0; fm < 4; fm++)
#pragma unroll
            for (int fn = 0; fn < 8; fn++) {
                const int nl = wn * 64 + fn * 8 + tg * 2;
#pragma unroll
                for (int half = 0; half < 2; half++) {
                    const int ml = wm * 64 + fm * 16 + g + half * 8;
                    smt[(nl)     * 136 + ml] = __float2half(acc[fm][fn][half * 2]);
                    smt[(nl + 1) * 136 + ml] = __float2half(acc[fm][fn][half * 2 + 1]);
                }
            }
        __syncthreads();
        const int b = m0 >> 11, ml0 = m0 & (SS - 1);
        const size_t rowbase = (size_t)b * DD * SS + (size_t)(n0 + threadIdx.x) * SS + ml0;
#pragma unroll
        for (int c16 = 0; c16 < 16; c16++) {
            uint4 v = *(uint4*)(smt + threadIdx.x * 136 + c16 * 8);
            *(uint4*)(g_vT + rowbase + c16 * 8) = v;
        }
        return;
    }

    // ---- causal scores tile ----
    int it = (int)floorf((sqrtf(8.0f * (float)t + 1.0f) - 1.0f) * 0.5f);
    while ((it + 1) * (it + 2) / 2 <= t) ++it;
    while (it * (it + 1) / 2 > t) --it;
    const int jt = t - it * (it + 1) / 2;
    const int b = blockIdx.y;
    const int m0 = it * 128, n0 = jt * 128;

    float acc[4][8][4];
    ZERO_ACC(acc);

    const size_t ao = ((size_t)b * SS + m0) * DD;
    const size_t bo = ((size_t)b * SS + n0) * DD;
    mma_mainloop(g_q + ao, g_k + bo, DD, DD, DD / 64, smem, acc);

    __half* C = g_ph + (size_t)b * SS * SS;
    const float alpha = 1.0f / 32.0f;
    const bool diag = (it == jt);

#pragma unroll
    for (int fm = 0; fm < 4; fm++) {
#pragma unroll
        for (int half = 0; half < 2; half++) {
            const int m = m0 + wm * 64 + fm * 16 + g + half * 8;
            float rsum = 0.0f;
#pragma unroll
            for (int fn = 0; fn < 8; fn++) {
                const int n = n0 + wn * 64 + fn * 8 + tg * 2;
                float e0 = __expf(acc[fm][fn][half * 2] * alpha);
                float e1 = __expf(acc[fm][fn][half * 2 + 1] * alpha);
                if (diag) {
                    if (n > m) e0 = 0.0f;
                    if (n + 1 > m) e1 = 0.0f;
                }
                rsum += e0 + e1;
                __half2 h2; h2.x = __float2half(e0); h2.y = __float2half(e1);
                *(__half2*)(C + (size_t)m * SS + n) = h2;
            }
            // reduce across the 4 tg lanes (same row m)
            rsum += __shfl_xor_sync(0xffffffffu, rsum, 1);
            rsum += __shfl_xor_sync(0xffffffffu, rsum, 2);
            if (tg == 0) atomicAdd(&g_sum[b * SS + m], rsum);
        }
    }
}

// ---------------------------------------------------------------------------
// Kernel 3: O = (p~ @ V) / row_sum.  Longest row-tiles first.
// ---------------------------------------------------------------------------
__global__ __launch_bounds__(128, 2) void pv_mma(float* __restrict__ out) {
    extern __shared__ char smraw[];
    const uint32_t smem = (uint32_t)__cvta_generic_to_shared(smraw);
    const int b = blockIdx.z;
    const int it = (SS / 128 - 1) - blockIdx.y;   // 15..0, big tiles first
    const int m0 = it * 128;
    const int n0 = blockIdx.x * 128;
    const int nch = (it + 1) * 2;                 // kend = (it+1)*128, chunks of 64

    float acc[4][8][4];
    ZERO_ACC(acc);

    const size_t ao = ((size_t)b * SS + m0) * SS;
    const size_t bo = (size_t)b * DD * SS + (size_t)n0 * SS;
    mma_mainloop(g_ph + ao, g_vT + bo, SS, SS, nch, smem, acc);

    const int lane = threadIdx.x & 31, wid = threadIdx.x >> 5;
    const int wm = wid >> 1, wn = wid & 1;
    const int g = lane >> 2, tg = lane & 3;
    float* C = out + (size_t)b * SS * DD;

    float invm[4][2];
#pragma unroll
    for (int fm = 0; fm < 4; fm++)
#pragma unroll
        for (int half = 0; half < 2; half++)
            invm[fm][half] = 1.0f / g_sum[b * SS + m0 + wm * 64 + fm * 16 + g + half * 8];

#pragma unroll
    for (int fm = 0; fm < 4; fm++)
#pragma unroll
        for (int fn = 0; fn < 8; fn++) {
            const int n = n0 + wn * 64 + fn * 8 + tg * 2;
#pragma unroll
            for (int half = 0; half < 2; half++) {
                const int m = m0 + wm * 64 + fm * 16 + g + half * 8;
                float2 v;
                v.x = acc[fm][fn][half * 2]     * invm[fm][half];
                v.y = acc[fm][fn][half * 2 + 1] * invm[fm][half];
                *(float2*)(C + (size_t)m * DD + n) = v;
            }
        }
}

// ---------------------------------------------------------------------------
extern "C" void kernel_launch(void* const* d_in, const int* in_sizes, int n_in,
                              void* d_out, int out_size) {
    const float* x  = (const float*)d_in[0];
    const float* wq = (const float*)d_in[1];
    const float* wk = (const float*)d_in[2];
    const float* wv = (const float*)d_in[3];
    float* out = (float*)d_out;
    (void)in_sizes; (void)n_in; (void)out_size;

    static bool attr_done = false;
    if (!attr_done) {
        cudaFuncSetAttribute(qkv_mma,      cudaFuncAttributeMaxDynamicSharedMemorySize, SMEM_BYTES);
        cudaFuncSetAttribute(scores_v_mma, cudaFuncAttributeMaxDynamicSharedMemorySize, SMEM_BYTES);
        cudaFuncSetAttribute(pv_mma,       cudaFuncAttributeMaxDynamicSharedMemorySize, SMEM_BYTES);
        attr_done = true;
    }

    // 0) convert x, W to fp16; zero row sums
    convert_all<<<dim3(512, 4), 256>>>(x, wq, wk, wv);

    // 1) Q, K projections (z = 0, 1)
    qkv_mma<<<dim3(DD / 128, (BB * SS) / 128, 2), 128, SMEM_BYTES>>>();

    // 2) fused: causal scores (+row sums) AND V^T projection
    scores_v_mma<<<dim3(136 + 128, BB), 128, SMEM_BYTES>>>();

    // 3) O = (p~ @ V) / sum
    pv_mma<<<dim3(DD / 128, SS / 128, BB), 128, SMEM_BYTES>>>(out);
}

// round 16
// speedup vs baseline: 1.1157x; 1.1157x over previous
#include <cuda_runtime.h>
#include <cuda_fp16.h>
#include <cstdint>
#include <math.h>

#define BB 4
#define SS 2048
#define DD 1024

#define LDBY 144                    // smem row stride bytes (128B data + 16B pad)
#define TILE_BY (128 * LDBY)        // 18432 B : 128x64 fp16 tile
#define NSTAGE 3
#define STAGE_B (2 * TILE_BY)       // A, B per stage = 36864
#define SMEM_BYTES (NSTAGE * STAGE_B)   // 110592 per CTA; 2 CTAs/SM = 221184

// ---------------------------------------------------------------------------
// Scratch (__device__ globals; allocation-free rule)
// ---------------------------------------------------------------------------
__device__ __align__(16) __half g_x[BB*SS*DD];      // x fp16 [b*s][d]
__device__ __align__(16) __half g_wv[DD*DD];        // Wv fp16 [o][d]
__device__ __align__(16) __half g_wqT[DD*DD];       // Wq^T fp16 [d][o]
__device__ __align__(16) __half g_wkT[DD*DD];       // Wk^T fp16 [e][o]
__device__ __align__(16) __half g_G[DD*DD];         // G'[e][d] = (Wq^T Wk)[d,e]
__device__ __align__(16) __half g_t[BB*SS*DD];      // t = x G  [b*s][e]
__device__ __align__(16) __half g_vT[BB*DD*SS];     // V^T [b][d][s]
__device__ __align__(16) __half g_ph[BB*SS*SS];     // p~ = exp(s/32), causal-masked
__device__ __align__(16) float  g_sum[BB*SS];       // row sums (atomic-accumulated)

// ---------------------------------------------------------------------------
// PTX primitives
// ---------------------------------------------------------------------------
__device__ __forceinline__ void mma_f16(float* d, const uint32_t* a, const uint32_t* b) {
    asm volatile(
        "mma.sync.aligned.m16n8k16.row.col.f32.f16.f16.f32 "
        "{%0,%1,%2,%3}, {%4,%5,%6,%7}, {%8,%9}, {%0,%1,%2,%3};"
        : "+f"(d[0]), "+f"(d[1]), "+f"(d[2]), "+f"(d[3])
        : "r"(a[0]), "r"(a[1]), "r"(a[2]), "r"(a[3]), "r"(b[0]), "r"(b[1]));
}
#define LDSM4(r0, r1, r2, r3, addr) \
    asm volatile("ldmatrix.sync.aligned.m8n8.x4.shared.b16 {%0,%1,%2,%3}, [%4];" \
                 : "=r"(r0), "=r"(r1), "=r"(r2), "=r"(r3) : "r"(addr))
#define CP_ASYNC16(dst, src) \
    asm volatile("cp.async.cg.shared.global [%0], [%1], 16;" :: "r"(dst), "l"(src))
#define CP_COMMIT() asm volatile("cp.async.commit_group;" ::: "memory")
#define CP_WAIT1()  asm volatile("cp.async.wait_group 1;" ::: "memory")

// ---------------------------------------------------------------------------
// cp.async: one 128x64 fp16 tile (K-major, row stride ld elems). 128 threads.
// ---------------------------------------------------------------------------
__device__ __forceinline__ void g2s_tile(uint32_t dst, const __half* __restrict__ g,
                                         size_t ld, int k0, int tid) {
#pragma unroll
    for (int i = 0; i < 8; i++) {
        int slot = tid + (i << 7);      // 0..1023
        int row = slot >> 3;            // 0..127
        int c = slot & 7;               // 16B chunk
        CP_ASYNC16(dst + row * LDBY + c * 16, g + (size_t)row * ld + k0 + c * 8);
    }
}

// ---------------------------------------------------------------------------
// Mainloop: acc[4][8][4] += A[128,K] . B[128,K]^T  (fp16, K-chunk 64)
// 128 threads, 4 warps 2x2, warp tile 64x64, 3-stage cp.async pipeline,
// ONE __syncthreads per chunk (compute-then-prefetch ordering).
// ---------------------------------------------------------------------------
__device__ __forceinline__ void mma_mainloop(
    const __half* __restrict__ A, const __half* __restrict__ B,
    size_t lda, size_t ldb, int nch, uint32_t smem, float acc[4][8][4]) {

    const int tid = threadIdx.x;
    const int lane = tid & 31, wid = tid >> 5;
    const int wm = wid >> 1, wn = wid & 1;

    const uint32_t a_off = (uint32_t)(wm * 64 + (lane & 15)) * LDBY + ((lane & 16) ? 16u : 0u);
    const uint32_t b_off = (uint32_t)(wn * 64 + (lane & 7) + ((lane & 16) ? 8 : 0)) * LDBY
                         + ((lane & 8) ? 16u : 0u);

    // prologue: chunks 0, 1
#pragma unroll
    for (int s = 0; s < 2; s++) {
        if (s < nch) {
            uint32_t st = smem + s * STAGE_B;
            g2s_tile(st,           A, lda, s * 64, tid);
            g2s_tile(st + TILE_BY, B, ldb, s * 64, tid);
        }
        CP_COMMIT();
    }

    int sidx = 0;
    for (int c = 0; c < nch; c++) {
        CP_WAIT1();
        __syncthreads();

        const uint32_t st = smem + sidx * STAGE_B;
#pragma unroll
        for (int ks = 0; ks < 4; ks++) {
            const uint32_t ka = st + a_off + ks * 32;
            const uint32_t kb = st + TILE_BY + b_off + ks * 32;
            uint32_t ah[4][4], bb[8][2];
#pragma unroll
            for (int fm = 0; fm < 4; fm++)
                LDSM4(ah[fm][0], ah[fm][1], ah[fm][2], ah[fm][3], ka + fm * 16 * LDBY);
#pragma unroll
            for (int p = 0; p < 4; p++)
                LDSM4(bb[2*p][0], bb[2*p][1], bb[2*p+1][0], bb[2*p+1][1], kb + p * 16 * LDBY);
#pragma unroll
            for (int fm = 0; fm < 4; fm++)
#pragma unroll
                for (int fn = 0; fn < 8; fn++) mma_f16(acc[fm][fn], ah[fm], bb[fn]);
        }

        // prefetch chunk c+2 into stage (sidx+2)%3
        if (c + 2 < nch) {
            int s2 = sidx + 2; if (s2 >= NSTAGE) s2 -= NSTAGE;
            uint32_t stw = smem + s2 * STAGE_B;
            const int k0 = (c + 2) * 64;
            g2s_tile(stw,           A, lda, k0, tid);
            g2s_tile(stw + TILE_BY, B, ldb, k0, tid);
        }
        CP_COMMIT();
        if (++sidx == NSTAGE) sidx = 0;
    }
}

#define ZERO_ACC(acc) \
    do { _Pragma("unroll") for (int i = 0; i < 4; i++) \
         _Pragma("unroll") for (int j = 0; j < 8; j++) \
         _Pragma("unroll") for (int r = 0; r < 4; r++) (acc)[i][j][r] = 0.0f; } while (0)

// fp16 tile store epilogue: D[m][n], row stride ld
__device__ __forceinline__ void store_tile_f16(__half* D, size_t ld, int m0, int n0,
                                               float acc[4][8][4]) {
    const int lane = threadIdx.x & 31, wid = threadIdx.x >> 5;
    const int wm = wid >> 1, wn = wid & 1;
    const int g = lane >> 2, tg = lane & 3;
#pragma unroll
    for (int fm = 0; fm < 4; fm++)
#pragma unroll
        for (int fn = 0; fn < 8; fn++) {
            const int n = n0 + wn * 64 + fn * 8 + tg * 2;
#pragma unroll
            for (int half = 0; half < 2; half++) {
                const int m = m0 + wm * 64 + fm * 16 + g + half * 8;
                __half2 h2;
                h2.x = __float2half(acc[fm][fn][half * 2]);
                h2.y = __float2half(acc[fm][fn][half * 2 + 1]);
                *(__half2*)(D + (size_t)m * ld + n) = h2;
            }
        }
}

// ---------------------------------------------------------------------------
// Kernel 0: convert x -> fp16, Wv -> fp16; zero g_sum
// ---------------------------------------------------------------------------
__global__ __launch_bounds__(256) void convert_all(
    const float* __restrict__ x, const float* __restrict__ wv) {
    const int which = blockIdx.y;
    const float* src = (which == 0) ? x : wv;
    __half* dst = (which == 0) ? g_x : g_wv;
    const int n4 = ((which == 0) ? BB * SS * DD : DD * DD) >> 2;
    for (int i = blockIdx.x * 256 + threadIdx.x; i < n4; i += gridDim.x * 256) {
        float4 f = *(const float4*)(src + i * 4);
        __half2 h0, h1;
        h0.x = __float2half(f.x); h0.y = __float2half(f.y);
        h1.x = __float2half(f.z); h1.y = __float2half(f.w);
        uint2 v; v.x = *(uint32_t*)&h0; v.y = *(uint32_t*)&h1;
        *(uint2*)(dst + i * 4) = v;
    }
    if (which == 0) {
        for (int i = blockIdx.x * 256 + threadIdx.x; i < BB * SS; i += gridDim.x * 256)
            g_sum[i] = 0.0f;
    }
}

// ---------------------------------------------------------------------------
// Kernel 0b: transposed fp16 copies of Wq, Wk (32x32 smem tiles)
// ---------------------------------------------------------------------------
__global__ __launch_bounds__(256) void transpose_w(
    const float* __restrict__ wq, const float* __restrict__ wk) {
    const float* src = blockIdx.z ? wk : wq;
    __half* dst = blockIdx.z ? g_wkT : g_wqT;
    __shared__ float tile[32][33];
    const int x0 = blockIdx.x * 32, y0 = blockIdx.y * 32;
    const int tx = threadIdx.x & 31, ty = threadIdx.x >> 5;   // 32 x 8
#pragma unroll
    for (int j = ty; j < 32; j += 8)
        tile[j][tx] = src[(size_t)(y0 + j) * DD + x0 + tx];
    __syncthreads();
#pragma unroll
    for (int j = ty; j < 32; j += 8)
        dst[(size_t)(x0 + j) * DD + y0 + tx] = __float2half(tile[tx][j]);
}

// ---------------------------------------------------------------------------
// Kernel 1 (fused): t < 512 -> V^T projection tile;  t >= 512 -> G tile
//   G'[e][d] = sum_o Wk[o,e] Wq[o,d]   (scores bilinear form, B-operand-ready)
// ---------------------------------------------------------------------------
__global__ __launch_bounds__(128, 2) void vg_mma() {
    extern __shared__ char smraw[];
    const uint32_t smem = (uint32_t)__cvta_generic_to_shared(smraw);
    const int t = blockIdx.x;
    const int lane = threadIdx.x & 31, wid = threadIdx.x >> 5;
    const int wm = wid >> 1, wn = wid & 1;
    const int g = lane >> 2, tg = lane & 3;

    float acc[4][8][4];
    ZERO_ACC(acc);

    if (t < 512) {
        // ---- V^T projection ----
        const int n0 = (t & 7) * 128;
        const int m0 = (t >> 3) * 128;
        mma_mainloop(g_x + (size_t)m0 * DD, g_wv + (size_t)n0 * DD,
                     DD, DD, DD / 64, smem, acc);

        // transpose 128x128 tile through smem, then coalesced store to V^T
        __syncthreads();
        __half* smt = (__half*)smraw;         // [n_local][m_local], stride 136
#pragma unroll
        for (int fm = 0; fm < 4; fm++)
#pragma unroll
            for (int fn = 0; fn < 8; fn++) {
                const int nl = wn * 64 + fn * 8 + tg * 2;
#pragma unroll
                for (int half = 0; half < 2; half++) {
                    const int ml = wm * 64 + fm * 16 + g + half * 8;
                    smt[(nl)     * 136 + ml] = __float2half(acc[fm][fn][half * 2]);
                    smt[(nl + 1) * 136 + ml] = __float2half(acc[fm][fn][half * 2 + 1]);
                }
            }
        __syncthreads();
        const int b = m0 >> 11, ml0 = m0 & (SS - 1);
        const size_t rowbase = (size_t)b * DD * SS + (size_t)(n0 + threadIdx.x) * SS + ml0;
#pragma unroll
        for (int c16 = 0; c16 < 16; c16++) {
            uint4 v = *(uint4*)(smt + threadIdx.x * 136 + c16 * 8);
            *(uint4*)(g_vT + rowbase + c16 * 8) = v;
        }
    } else {
        // ---- G tile: C[e,d] = sum_o WkT[e,o] WqT[d,o] ----
        const int u = t - 512;                // 0..63
        const int d0 = (u & 7) * 128;
        const int e0 = (u >> 3) * 128;
        mma_mainloop(g_wkT + (size_t)e0 * DD, g_wqT + (size_t)d0 * DD,
                     DD, DD, DD / 64, smem, acc);
        store_tile_f16(g_G, DD, e0, d0, acc);
    }
}

// ---------------------------------------------------------------------------
// Kernel 2: t = x . G'^T   (t[m,e] = sum_d x[m,d] G'[e,d])
// ---------------------------------------------------------------------------
__global__ __launch_bounds__(128, 2) void t_mma() {
    extern __shared__ char smraw[];
    const uint32_t smem = (uint32_t)__cvta_generic_to_shared(smraw);
    const int m0 = blockIdx.y * 128;
    const int e0 = blockIdx.x * 128;

    float acc[4][8][4];
    ZERO_ACC(acc);

    mma_mainloop(g_x + (size_t)m0 * DD, g_G + (size_t)e0 * DD,
                 DD, DD, DD / 64, smem, acc);
    store_tile_f16(g_t, DD, m0, e0, acc);
}

// ---------------------------------------------------------------------------
// Kernel 3: causal scores s = t . x^T -> p~ = exp(s/32) fp16 + fused row sums
// Lower-triangular 128x128 tiles only (136 per batch).
// ---------------------------------------------------------------------------
__global__ __launch_bounds__(128, 2) void scores_mma() {
    extern __shared__ char smraw[];
    const uint32_t smem = (uint32_t)__cvta_generic_to_shared(smraw);
    const int t = blockIdx.x;
    int it = (int)floorf((sqrtf(8.0f * (float)t + 1.0f) - 1.0f) * 0.5f);
    while ((it + 1) * (it + 2) / 2 <= t) ++it;
    while (it * (it + 1) / 2 > t) --it;
    const int jt = t - it * (it + 1) / 2;
    const int b = blockIdx.y;
    const int m0 = it * 128, n0 = jt * 128;

    float acc[4][8][4];
    ZERO_ACC(acc);

    const size_t ao = ((size_t)b * SS + m0) * DD;
    const size_t bo = ((size_t)b * SS + n0) * DD;
    mma_mainloop(g_t + ao, g_x + bo, DD, DD, DD / 64, smem, acc);

    const int lane = threadIdx.x & 31, wid = threadIdx.x >> 5;
    const int wm = wid >> 1, wn = wid & 1;
    const int g = lane >> 2, tg = lane & 3;
    __half* C = g_ph + (size_t)b * SS * SS;
    const float alpha = 1.0f / 32.0f;
    const bool diag = (it == jt);

#pragma unroll
    for (int fm = 0; fm < 4; fm++) {
#pragma unroll
        for (int half = 0; half < 2; half++) {
            const int m = m0 + wm * 64 + fm * 16 + g + half * 8;
            float rsum = 0.0f;
#pragma unroll
            for (int fn = 0; fn < 8; fn++) {
                const int n = n0 + wn * 64 + fn * 8 + tg * 2;
                float e0 = __expf(acc[fm][fn][half * 2] * alpha);
                float e1 = __expf(acc[fm][fn][half * 2 + 1] * alpha);
                if (diag) {
                    if (n > m) e0 = 0.0f;
                    if (n + 1 > m) e1 = 0.0f;
                }
                rsum += e0 + e1;
                __half2 h2; h2.x = __float2half(e0); h2.y = __float2half(e1);
                *(__half2*)(C + (size_t)m * SS + n) = h2;
            }
            rsum += __shfl_xor_sync(0xffffffffu, rsum, 1);
            rsum += __shfl_xor_sync(0xffffffffu, rsum, 2);
            if (tg == 0) atomicAdd(&g_sum[b * SS + m], rsum);
        }
    }
}

// ---------------------------------------------------------------------------
// Kernel 4: O = (p~ @ V) / row_sum.  Longest row-tiles first.
// ---------------------------------------------------------------------------
__global__ __launch_bounds__(128, 2) void pv_mma(float* __restrict__ out) {
    extern __shared__ char smraw[];
    const uint32_t smem = (uint32_t)__cvta_generic_to_shared(smraw);
    const int b = blockIdx.z;
    const int it = (SS / 128 - 1) - blockIdx.y;   // 15..0, big tiles first
    const int m0 = it * 128;
    const int n0 = blockIdx.x * 128;
    const int nch = (it + 1) * 2;                 // kend = (it+1)*128, chunks of 64

    float acc[4][8][4];
    ZERO_ACC(acc);

    const size_t ao = ((size_t)b * SS + m0) * SS;
    const size_t bo = (size_t)b * DD * SS + (size_t)n0 * SS;
    mma_mainloop(g_ph + ao, g_vT + bo, SS, SS, nch, smem, acc);

    const int lane = threadIdx.x & 31, wid = threadIdx.x >> 5;
    const int wm = wid >> 1, wn = wid & 1;
    const int g = lane >> 2, tg = lane & 3;
    float* C = out + (size_t)b * SS * DD;

    float invm[4][2];
#pragma unroll
    for (int fm = 0; fm < 4; fm++)
#pragma unroll
        for (int half = 0; half < 2; half++)
            invm[fm][half] = 1.0f / g_sum[b * SS + m0 + wm * 64 + fm * 16 + g + half * 8];

#pragma unroll
    for (int fm = 0; fm < 4; fm++)
#pragma unroll
        for (int fn = 0; fn < 8; fn++) {
            const int n = n0 + wn * 64 + fn * 8 + tg * 2;
#pragma unroll
            for (int half = 0; half < 2; half++) {
                const int m = m0 + wm * 64 + fm * 16 + g + half * 8;
                float2 v;
                v.x = acc[fm][fn][half * 2]     * invm[fm][half];
                v.y = acc[fm][fn][half * 2 + 1] * invm[fm][half];
                *(float2*)(C + (size_t)m * DD + n) = v;
            }
        }
}

// ---------------------------------------------------------------------------
extern "C" void kernel_launch(void* const* d_in, const int* in_sizes, int n_in,
                              void* d_out, int out_size) {
    const float* x  = (const float*)d_in[0];
    const float* wq = (const float*)d_in[1];
    const float* wk = (const float*)d_in[2];
    const float* wv = (const float*)d_in[3];
    float* out = (float*)d_out;
    (void)in_sizes; (void)n_in; (void)out_size;

    static bool attr_done = false;
    if (!attr_done) {
        cudaFuncSetAttribute(vg_mma,     cudaFuncAttributeMaxDynamicSharedMemorySize, SMEM_BYTES);
        cudaFuncSetAttribute(t_mma,      cudaFuncAttributeMaxDynamicSharedMemorySize, SMEM_BYTES);
        cudaFuncSetAttribute(scores_mma, cudaFuncAttributeMaxDynamicSharedMemorySize, SMEM_BYTES);
        cudaFuncSetAttribute(pv_mma,     cudaFuncAttributeMaxDynamicSharedMemorySize, SMEM_BYTES);
        attr_done = true;
    }

    // 0) convert x, Wv to fp16; zero row sums
    convert_all<<<dim3(512, 2), 256>>>(x, wv);

    // 0b) transposed fp16 Wq, Wk
    transpose_w<<<dim3(32, 32, 2), 256>>>(wq, wk);

    // 1) fused: V^T projection (512 CTAs) + G = Wq^T Wk (64 CTAs)
    vg_mma<<<dim3(576), 128, SMEM_BYTES>>>();

    // 2) t = x . G
    t_mma<<<dim3(DD / 128, (BB * SS) / 128), 128, SMEM_BYTES>>>();

    // 3) causal scores s = t . x^T -> exp(s/32) fp16 (masked) + row sums
    const int ntri = (SS / 128) * (SS / 128 + 1) / 2;   // 136
    scores_mma<<<dim3(ntri, BB), 128, SMEM_BYTES>>>();

    // 4) O = (p~ @ V) / sum
    pv_mma<<<dim3(DD / 128, SS / 128, BB), 128, SMEM_BYTES>>>(out);
}

// round 17
// speedup vs baseline: 1.1165x; 1.0007x over previous
#include <cuda_runtime.h>
#include <cuda_fp16.h>
#include <cstdint>
#include <math.h>

#define BB 4
#define SS 2048
#define DD 1024

#define LDBY 144                    // smem row stride bytes (128B data + 16B pad)
#define TILE_BY (128 * LDBY)        // 18432 B : 128x64 fp16 tile
#define NSTAGE 3
#define STAGE_B (2 * TILE_BY)       // A, B per stage = 36864
#define SMEM_BYTES (NSTAGE * STAGE_B)   // 110592 per CTA; 2 CTAs/SM = 221184

// ---------------------------------------------------------------------------
// Scratch (__device__ globals; allocation-free rule)
// ---------------------------------------------------------------------------
__device__ __align__(16) __half g_x[BB*SS*DD];      // x fp16 [b*s][d]
__device__ __align__(16) __half g_wv[DD*DD];        // Wv fp16 [o][d]
__device__ __align__(16) __half g_wqT[DD*DD];       // Wq^T fp16 [d][o]
__device__ __align__(16) __half g_wkT[DD*DD];       // Wk^T fp16 [e][o]
__device__ __align__(16) __half g_G[DD*DD];         // G'[e][d] = (Wq^T Wk)[d,e]
__device__ __align__(16) __half g_t[BB*SS*DD];      // t = x G  [b*s][e]
__device__ __align__(16) __half g_vT[BB*DD*SS];     // V^T [b][d][s]
__device__ __align__(16) __half g_ph[BB*SS*SS];     // p~ = exp(s/32), causal-masked
__device__ __align__(16) float  g_sum[BB*SS];       // row sums (atomic-accumulated)

// pv split-unit table (big-first): it, start chunk, chunk count
__device__ __constant__ int c_pv_it[24] = {15,15, 7,14,14,13,13, 6,12,12,11,11, 5,10,10, 9, 9, 4, 8, 8, 3, 2, 1, 0};
__device__ __constant__ int c_pv_c0[24] = { 0,16, 0, 0,15, 0,14, 0, 0,13, 0,12, 0, 0,11, 0,10, 0, 0, 9, 0, 0, 0, 0};
__device__ __constant__ int c_pv_nc[24] = {16,16,16,15,15,14,14,14,13,13,12,12,12,11,11,10,10,10, 9, 9, 8, 6, 4, 2};

// ---------------------------------------------------------------------------
// PTX primitives
// ---------------------------------------------------------------------------
__device__ __forceinline__ void mma_f16(float* d, const uint32_t* a, const uint32_t* b) {
    asm volatile(
        "mma.sync.aligned.m16n8k16.row.col.f32.f16.f16.f32 "
        "{%0,%1,%2,%3}, {%4,%5,%6,%7}, {%8,%9}, {%0,%1,%2,%3};"
        : "+f"(d[0]), "+f"(d[1]), "+f"(d[2]), "+f"(d[3])
        : "r"(a[0]), "r"(a[1]), "r"(a[2]), "r"(a[3]), "r"(b[0]), "r"(b[1]));
}
#define LDSM4(r0, r1, r2, r3, addr) \
    asm volatile("ldmatrix.sync.aligned.m8n8.x4.shared.b16 {%0,%1,%2,%3}, [%4];" \
                 : "=r"(r0), "=r"(r1), "=r"(r2), "=r"(r3) : "r"(addr))
#define CP_ASYNC16(dst, src) \
    asm volatile("cp.async.cg.shared.global [%0], [%1], 16;" :: "r"(dst), "l"(src))
#define CP_COMMIT() asm volatile("cp.async.commit_group;" ::: "memory")
#define CP_WAIT1()  asm volatile("cp.async.wait_group 1;" ::: "memory")

// ---------------------------------------------------------------------------
// cp.async: one 128x64 fp16 tile (K-major, row stride ld elems). 128 threads.
// ---------------------------------------------------------------------------
__device__ __forceinline__ void g2s_tile(uint32_t dst, const __half* __restrict__ g,
                                         size_t ld, int k0, int tid) {
#pragma unroll
    for (int i = 0; i < 8; i++) {
        int slot = tid + (i << 7);      // 0..1023
        int row = slot >> 3;            // 0..127
        int c = slot & 7;               // 16B chunk
        CP_ASYNC16(dst + row * LDBY + c * 16, g + (size_t)row * ld + k0 + c * 8);
    }
}

// ---------------------------------------------------------------------------
// Mainloop: acc[4][8][4] += A[128,K] . B[128,K]^T  (fp16, K-chunk 64)
// 128 threads, 4 warps 2x2, warp tile 64x64, 3-stage cp.async pipeline,
// ONE __syncthreads per chunk (compute-then-prefetch ordering).
// ---------------------------------------------------------------------------
__device__ __forceinline__ void mma_mainloop(
    const __half* __restrict__ A, const __half* __restrict__ B,
    size_t lda, size_t ldb, int nch, uint32_t smem, float acc[4][8][4]) {

    const int tid = threadIdx.x;
    const int lane = tid & 31, wid = tid >> 5;
    const int wm = wid >> 1, wn = wid & 1;

    const uint32_t a_off = (uint32_t)(wm * 64 + (lane & 15)) * LDBY + ((lane & 16) ? 16u : 0u);
    const uint32_t b_off = (uint32_t)(wn * 64 + (lane & 7) + ((lane & 16) ? 8 : 0)) * LDBY
                         + ((lane & 8) ? 16u : 0u);

    // prologue: chunks 0, 1
#pragma unroll
    for (int s = 0; s < 2; s++) {
        if (s < nch) {
            uint32_t st = smem + s * STAGE_B;
            g2s_tile(st,           A, lda, s * 64, tid);
            g2s_tile(st + TILE_BY, B, ldb, s * 64, tid);
        }
        CP_COMMIT();
    }

    int sidx = 0;
    for (int c = 0; c < nch; c++) {
        CP_WAIT1();
        __syncthreads();

        const uint32_t st = smem + sidx * STAGE_B;
#pragma unroll
        for (int ks = 0; ks < 4; ks++) {
            const uint32_t ka = st + a_off + ks * 32;
            const uint32_t kb = st + TILE_BY + b_off + ks * 32;
            uint32_t ah[4][4], bb[8][2];
#pragma unroll
            for (int fm = 0; fm < 4; fm++)
                LDSM4(ah[fm][0], ah[fm][1], ah[fm][2], ah[fm][3], ka + fm * 16 * LDBY);
#pragma unroll
            for (int p = 0; p < 4; p++)
                LDSM4(bb[2*p][0], bb[2*p][1], bb[2*p+1][0], bb[2*p+1][1], kb + p * 16 * LDBY);
#pragma unroll
            for (int fm = 0; fm < 4; fm++)
#pragma unroll
                for (int fn = 0; fn < 8; fn++) mma_f16(acc[fm][fn], ah[fm], bb[fn]);
        }

        // prefetch chunk c+2 into stage (sidx+2)%3
        if (c + 2 < nch) {
            int s2 = sidx + 2; if (s2 >= NSTAGE) s2 -= NSTAGE;
            uint32_t stw = smem + s2 * STAGE_B;
            const int k0 = (c + 2) * 64;
            g2s_tile(stw,           A, lda, k0, tid);
            g2s_tile(stw + TILE_BY, B, ldb, k0, tid);
        }
        CP_COMMIT();
        if (++sidx == NSTAGE) sidx = 0;
    }
}

#define ZERO_ACC(acc) \
    do { _Pragma("unroll") for (int i = 0; i < 4; i++) \
         _Pragma("unroll") for (int j = 0; j < 8; j++) \
         _Pragma("unroll") for (int r = 0; r < 4; r++) (acc)[i][j][r] = 0.0f; } while (0)

// fp16 tile store epilogue: D[m][n], row stride ld
__device__ __forceinline__ void store_tile_f16(__half* D, size_t ld, int m0, int n0,
                                               float acc[4][8][4]) {
    const int lane = threadIdx.x & 31, wid = threadIdx.x >> 5;
    const int wm = wid >> 1, wn = wid & 1;
    const int g = lane >> 2, tg = lane & 3;
#pragma unroll
    for (int fm = 0; fm < 4; fm++)
#pragma unroll
        for (int fn = 0; fn < 8; fn++) {
            const int n = n0 + wn * 64 + fn * 8 + tg * 2;
#pragma unroll
            for (int half = 0; half < 2; half++) {
                const int m = m0 + wm * 64 + fm * 16 + g + half * 8;
                __half2 h2;
                h2.x = __float2half(acc[fm][fn][half * 2]);
                h2.y = __float2half(acc[fm][fn][half * 2 + 1]);
                *(__half2*)(D + (size_t)m * ld + n) = h2;
            }
        }
}

// ---------------------------------------------------------------------------
// Kernel 0: convert x -> fp16, Wv -> fp16; zero g_sum; zero out
// ---------------------------------------------------------------------------
__global__ __launch_bounds__(256) void convert_all(
    const float* __restrict__ x, const float* __restrict__ wv, float* __restrict__ out) {
    const int which = blockIdx.y;
    if (which == 2) {
        // zero out buffer (pv accumulates atomically)
        float4 z = make_float4(0.f, 0.f, 0.f, 0.f);
        const int n4 = (BB * SS * DD) >> 2;
        for (int i = blockIdx.x * 256 + threadIdx.x; i < n4; i += gridDim.x * 256)
            *(float4*)(out + i * 4) = z;
        return;
    }
    const float* src = (which == 0) ? x : wv;
    __half* dst = (which == 0) ? g_x : g_wv;
    const int n4 = ((which == 0) ? BB * SS * DD : DD * DD) >> 2;
    for (int i = blockIdx.x * 256 + threadIdx.x; i < n4; i += gridDim.x * 256) {
        float4 f = *(const float4*)(src + i * 4);
        __half2 h0, h1;
        h0.x = __float2half(f.x); h0.y = __float2half(f.y);
        h1.x = __float2half(f.z); h1.y = __float2half(f.w);
        uint2 v; v.x = *(uint32_t*)&h0; v.y = *(uint32_t*)&h1;
        *(uint2*)(dst + i * 4) = v;
    }
    if (which == 0) {
        for (int i = blockIdx.x * 256 + threadIdx.x; i < BB * SS; i += gridDim.x * 256)
            g_sum[i] = 0.0f;
    }
}

// ---------------------------------------------------------------------------
// Kernel 0b: transposed fp16 copies of Wq, Wk (32x32 smem tiles)
// ---------------------------------------------------------------------------
__global__ __launch_bounds__(256) void transpose_w(
    const float* __restrict__ wq, const float* __restrict__ wk) {
    const float* src = blockIdx.z ? wk : wq;
    __half* dst = blockIdx.z ? g_wkT : g_wqT;
    __shared__ float tile[32][33];
    const int x0 = blockIdx.x * 32, y0 = blockIdx.y * 32;
    const int tx = threadIdx.x & 31, ty = threadIdx.x >> 5;   // 32 x 8
#pragma unroll
    for (int j = ty; j < 32; j += 8)
        tile[j][tx] = src[(size_t)(y0 + j) * DD + x0 + tx];
    __syncthreads();
#pragma unroll
    for (int j = ty; j < 32; j += 8)
        dst[(size_t)(x0 + j) * DD + y0 + tx] = __float2half(tile[tx][j]);
}

// ---------------------------------------------------------------------------
// Kernel 1 (fused): t < 512 -> V^T projection tile;  t >= 512 -> G tile
// ---------------------------------------------------------------------------
__global__ __launch_bounds__(128, 2) void vg_mma() {
    extern __shared__ char smraw[];
    const uint32_t smem = (uint32_t)__cvta_generic_to_shared(smraw);
    const int t = blockIdx.x;
    const int lane = threadIdx.x & 31, wid = threadIdx.x >> 5;
    const int wm = wid >> 1, wn = wid & 1;
    const int g = lane >> 2, tg = lane & 3;

    float acc[4][8][4];
    ZERO_ACC(acc);

    if (t < 512) {
        // ---- V^T projection ----
        const int n0 = (t & 7) * 128;
        const int m0 = (t >> 3) * 128;
        mma_mainloop(g_x + (size_t)m0 * DD, g_wv + (size_t)n0 * DD,
                     DD, DD, DD / 64, smem, acc);

        // transpose 128x128 tile through smem, then coalesced store to V^T
        __syncthreads();
        __half* smt = (__half*)smraw;         // [n_local][m_local], stride 136
#pragma unroll
        for (int fm = 0; fm < 4; fm++)
#pragma unroll
            for (int fn = 0; fn < 8; fn++) {
                const int nl = wn * 64 + fn * 8 + tg * 2;
#pragma unroll
                for (int half = 0; half < 2; half++) {
                    const int ml = wm * 64 + fm * 16 + g + half * 8;
                    smt[(nl)     * 136 + ml] = __float2half(acc[fm][fn][half * 2]);
                    smt[(nl + 1) * 136 + ml] = __float2half(acc[fm][fn][half * 2 + 1]);
                }
            }
        __syncthreads();
        const int b = m0 >> 11, ml0 = m0 & (SS - 1);
        const size_t rowbase = (size_t)b * DD * SS + (size_t)(n0 + threadIdx.x) * SS + ml0;
#pragma unroll
        for (int c16 = 0; c16 < 16; c16++) {
            uint4 v = *(uint4*)(smt + threadIdx.x * 136 + c16 * 8);
            *(uint4*)(g_vT + rowbase + c16 * 8) = v;
        }
    } else {
        // ---- G tile: C[e,d] = sum_o WkT[e,o] WqT[d,o] ----
        const int u = t - 512;                // 0..63
        const int d0 = (u & 7) * 128;
        const int e0 = (u >> 3) * 128;
        mma_mainloop(g_wkT + (size_t)e0 * DD, g_wqT + (size_t)d0 * DD,
                     DD, DD, DD / 64, smem, acc);
        store_tile_f16(g_G, DD, e0, d0, acc);
    }
}

// ---------------------------------------------------------------------------
// Kernel 2: t = x . G'^T
// ---------------------------------------------------------------------------
__global__ __launch_bounds__(128, 2) void t_mma() {
    extern __shared__ char smraw[];
    const uint32_t smem = (uint32_t)__cvta_generic_to_shared(smraw);
    const int m0 = blockIdx.y * 128;
    const int e0 = blockIdx.x * 128;

    float acc[4][8][4];
    ZERO_ACC(acc);

    mma_mainloop(g_x + (size_t)m0 * DD, g_G + (size_t)e0 * DD,
                 DD, DD, DD / 64, smem, acc);
    store_tile_f16(g_t, DD, m0, e0, acc);
}

// ---------------------------------------------------------------------------
// Kernel 3: causal scores s = t . x^T -> p~ = exp(s/32) fp16 + fused row sums
// ---------------------------------------------------------------------------
__global__ __launch_bounds__(128, 2) void scores_mma() {
    extern __shared__ char smraw[];
    const uint32_t smem = (uint32_t)__cvta_generic_to_shared(smraw);
    const int t = blockIdx.x;
    int it = (int)floorf((sqrtf(8.0f * (float)t + 1.0f) - 1.0f) * 0.5f);
    while ((it + 1) * (it + 2) / 2 <= t) ++it;
    while (it * (it + 1) / 2 > t) --it;
    const int jt = t - it * (it + 1) / 2;
    const int b = blockIdx.y;
    const int m0 = it * 128, n0 = jt * 128;

    float acc[4][8][4];
    ZERO_ACC(acc);

    const size_t ao = ((size_t)b * SS + m0) * DD;
    const size_t bo = ((size_t)b * SS + n0) * DD;
    mma_mainloop(g_t + ao, g_x + bo, DD, DD, DD / 64, smem, acc);

    const int lane = threadIdx.x & 31, wid = threadIdx.x >> 5;
    const int wm = wid >> 1, wn = wid & 1;
    const int g = lane >> 2, tg = lane & 3;
    __half* C = g_ph + (size_t)b * SS * SS;
    const float alpha = 1.0f / 32.0f;
    const bool diag = (it == jt);

#pragma unroll
    for (int fm = 0; fm < 4; fm++) {
#pragma unroll
        for (int half = 0; half < 2; half++) {
            const int m = m0 + wm * 64 + fm * 16 + g + half * 8;
            float rsum = 0.0f;
#pragma unroll
            for (int fn = 0; fn < 8; fn++) {
                const int n = n0 + wn * 64 + fn * 8 + tg * 2;
                float e0 = __expf(acc[fm][fn][half * 2] * alpha);
                float e1 = __expf(acc[fm][fn][half * 2 + 1] * alpha);
                if (diag) {
                    if (n > m) e0 = 0.0f;
                    if (n + 1 > m) e1 = 0.0f;
                }
                rsum += e0 + e1;
                __half2 h2; h2.x = __float2half(e0); h2.y = __float2half(e1);
                *(__half2*)(C + (size_t)m * SS + n) = h2;
            }
            rsum += __shfl_xor_sync(0xffffffffu, rsum, 1);
            rsum += __shfl_xor_sync(0xffffffffu, rsum, 2);
            if (tg == 0) atomicAdd(&g_sum[b * SS + m], rsum);
        }
    }
}

// ---------------------------------------------------------------------------
// Kernel 4: O += (p~[c0*64 : c0*64+nc*64] @ V) / row_sum   (split-K units)
// grid = (32 = n*b, 24 = unit big-first)
// ---------------------------------------------------------------------------
__global__ __launch_bounds__(128, 2) void pv_mma(float* __restrict__ out) {
    extern __shared__ char smraw[];
    const uint32_t smem = (uint32_t)__cvta_generic_to_shared(smraw);
    const int n0 = (blockIdx.x & 7) * 128;
    const int b  = blockIdx.x >> 3;
    const int u  = blockIdx.y;
    const int it = c_pv_it[u];
    const int c0 = c_pv_c0[u];
    const int nc = c_pv_nc[u];
    const int m0 = it * 128;

    float acc[4][8][4];
    ZERO_ACC(acc);

    const size_t ao = ((size_t)b * SS + m0) * SS + (size_t)c0 * 64;
    const size_t bo = (size_t)b * DD * SS + (size_t)n0 * SS + (size_t)c0 * 64;
    mma_mainloop(g_ph + ao, g_vT + bo, SS, SS, nc, smem, acc);

    const int lane = threadIdx.x & 31, wid = threadIdx.x >> 5;
    const int wm = wid >> 1, wn = wid & 1;
    const int g = lane >> 2, tg = lane & 3;
    float* C = out + (size_t)b * SS * DD;

    float invm[4][2];
#pragma unroll
    for (int fm = 0; fm < 4; fm++)
#pragma unroll
        for (int half = 0; half < 2; half++)
            invm[fm][half] = 1.0f / g_sum[b * SS + m0 + wm * 64 + fm * 16 + g + half * 8];

#pragma unroll
    for (int fm = 0; fm < 4; fm++)
#pragma unroll
        for (int fn = 0; fn < 8; fn++) {
            const int n = n0 + wn * 64 + fn * 8 + tg * 2;
#pragma unroll
            for (int half = 0; half < 2; half++) {
                const int m = m0 + wm * 64 + fm * 16 + g + half * 8;
                atomicAdd(&C[(size_t)m * DD + n],     acc[fm][fn][half * 2]     * invm[fm][half]);
                atomicAdd(&C[(size_t)m * DD + n + 1], acc[fm][fn][half * 2 + 1] * invm[fm][half]);
            }
        }
}

// ---------------------------------------------------------------------------
extern "C" void kernel_launch(void* const* d_in, const int* in_sizes, int n_in,
                              void* d_out, int out_size) {
    const float* x  = (const float*)d_in[0];
    const float* wq = (const float*)d_in[1];
    const float* wk = (const float*)d_in[2];
    const float* wv = (const float*)d_in[3];
    float* out = (float*)d_out;
    (void)in_sizes; (void)n_in; (void)out_size;

    static bool attr_done = false;
    if (!attr_done) {
        cudaFuncSetAttribute(vg_mma,     cudaFuncAttributeMaxDynamicSharedMemorySize, SMEM_BYTES);
        cudaFuncSetAttribute(t_mma,      cudaFuncAttributeMaxDynamicSharedMemorySize, SMEM_BYTES);
        cudaFuncSetAttribute(scores_mma, cudaFuncAttributeMaxDynamicSharedMemorySize, SMEM_BYTES);
        cudaFuncSetAttribute(pv_mma,     cudaFuncAttributeMaxDynamicSharedMemorySize, SMEM_BYTES);
        attr_done = true;
    }

    // 0) convert x, Wv to fp16; zero row sums; zero out (pv accumulates)
    convert_all<<<dim3(512, 3), 256>>>(x, wv, out);

    // 0b) transposed fp16 Wq, Wk
    transpose_w<<<dim3(32, 32, 2), 256>>>(wq, wk);

    // 1) fused: V^T projection (512 CTAs) + G = Wq^T Wk (64 CTAs)
    vg_mma<<<dim3(576), 128, SMEM_BYTES>>>();

    // 2) t = x . G
    t_mma<<<dim3(DD / 128, (BB * SS) / 128), 128, SMEM_BYTES>>>();

    // 3) causal scores s = t . x^T -> exp(s/32) fp16 (masked) + row sums
    const int ntri = (SS / 128) * (SS / 128 + 1) / 2;   // 136
    scores_mma<<<dim3(ntri, BB), 128, SMEM_BYTES>>>();

    // 4) O += (p~ @ V) / sum   (balanced split-K units, big-first)
    pv_mma<<<dim3(32, 24), 128, SMEM_BYTES>>>(out);
}